// round 6
// baseline (speedup 1.0000x reference)
#include <cuda_runtime.h>
#include <cuda_fp16.h>
#include <cstdint>

#define N_NODES 100000
#define N_EDGES 1600000
#define D_FEAT 48

#define SCAN_BS 512
#define SCAN_BLOCKS ((N_NODES + SCAN_BS - 1) / SCAN_BS)   // 196

// ---- static device scratch (no allocation allowed) ----
__device__ int   g_row[N_NODES + 1];
__device__ int   g_cur[N_NODES];
__device__ int   g_csr[N_EDGES];
__device__ int   g_bsum[SCAN_BLOCKS];
__device__ uint4 g_h0[N_NODES * 6];      // features as half [N,48] = 96B/row
__device__ uint4 g_buf0[N_NODES * 6];
__device__ uint4 g_buf1[N_NODES * 6];

// ---------------------------------------------------------------------------
// Fused: zero degree counters + convert fp32 features -> half.
// Grid covers N_NODES*12 threads (one float4 each); first N_NODES+1 also zero.
// ---------------------------------------------------------------------------
__global__ void prep_kernel(const float4* __restrict__ feat) {
    int i = blockIdx.x * blockDim.x + threadIdx.x;
    if (i <= N_NODES) g_row[i] = 0;
    if (i < N_NODES * 12) {
        float4 v = feat[i];
        __half2 a = __floats2half2_rn(v.x, v.y);
        __half2 b = __floats2half2_rn(v.z, v.w);
        uint2 u;
        u.x = *reinterpret_cast<unsigned*>(&a);
        u.y = *reinterpret_cast<unsigned*>(&b);
        ((uint2*)g_h0)[i] = u;
    }
}

// ---------------------------------------------------------------------------
// CSR build
// ---------------------------------------------------------------------------
__global__ void hist_kernel(const int4* __restrict__ dst4, int n_quads) {
    int q = blockIdx.x * blockDim.x + threadIdx.x;
    if (q < n_quads) {
        int4 d = dst4[q];
        atomicAdd(&g_row[d.x], 1);
        atomicAdd(&g_row[d.y], 1);
        atomicAdd(&g_row[d.z], 1);
        atomicAdd(&g_row[d.w], 1);
    }
}

__global__ void scanA_kernel() {
    __shared__ int s[SCAN_BS];
    int t = threadIdx.x;
    int i = blockIdx.x * SCAN_BS + t;
    s[t] = (i < N_NODES) ? g_row[i] : 0;
    __syncthreads();
    for (int off = SCAN_BS / 2; off > 0; off >>= 1) {
        if (t < off) s[t] += s[t + off];
        __syncthreads();
    }
    if (t == 0) g_bsum[blockIdx.x] = s[0];
}

// Local scan; each block computes its own global prefix by summing the
// block aggregates below it (196 ints -- trivial). No serial middle kernel.
__global__ void scanC_kernel() {
    __shared__ int s[SCAN_BS];
    __shared__ int p[256];
    int t = threadIdx.x;
    int bid = blockIdx.x;

    // prefix of block sums below bid
    if (t < 256) p[t] = (t < bid) ? g_bsum[t] : 0;
    __syncthreads();
    for (int off = 128; off > 0; off >>= 1) {
        if (t < off) p[t] += p[t + off];
        __syncthreads();
    }
    int blockPrefix = p[0];

    int i = bid * SCAN_BS + t;
    int v = (i < N_NODES) ? g_row[i] : 0;
    s[t] = v;
    __syncthreads();
    for (int off = 1; off < SCAN_BS; off <<= 1) {
        int x = (t >= off) ? s[t - off] : 0;
        __syncthreads();
        s[t] += x;
        __syncthreads();
    }
    if (i < N_NODES) {
        int excl = blockPrefix + s[t] - v;
        g_row[i] = excl;
        g_cur[i] = excl;
    }
    if (i == N_NODES - 1) g_row[N_NODES] = blockPrefix + s[t];
}

__global__ void fill_kernel(const int* __restrict__ src,
                            const int* __restrict__ dst, int n_edges) {
    int e = blockIdx.x * blockDim.x + threadIdx.x;
    if (e < n_edges) {
        int d = dst[e];
        int pos = atomicAdd(&g_cur[d], 1);
        g_csr[pos] = src[e];
    }
}

// ---------------------------------------------------------------------------
// GCN layer over half input. FINAL=false: half out + relu. FINAL=true: fp32 out.
// 64 nodes/block x 6 chunk-threads (16B half chunks = 8 feats each).
// ---------------------------------------------------------------------------
#define LH_NODES 64
#define LH_THREADS (LH_NODES * 6)    // 384
#define LH_TILE 2048

template <bool FINAL>
__global__ void __launch_bounds__(LH_THREADS)
layer_h(const uint4* __restrict__ h, uint4* __restrict__ outh,
        float4* __restrict__ outf) {
    __shared__ int s_idx[LH_TILE];
    int node0 = blockIdx.x * LH_NODES;
    int tid = threadIdx.x;
    int nl = tid / 6, c = tid - nl * 6;
    int node = node0 + nl;

    int lastn  = min(node0 + LH_NODES, N_NODES);
    int blkBeg = g_row[node0];
    int blkEnd = g_row[lastn];
    int beg = 0, end = 0;
    if (node < N_NODES) { beg = g_row[node]; end = g_row[node + 1]; }

    float a0 = 0.f, a1 = 0.f, a2 = 0.f, a3 = 0.f;
    float a4 = 0.f, a5 = 0.f, a6 = 0.f, a7 = 0.f;

    for (int base = blkBeg; base < blkEnd; base += LH_TILE) {
        int cnt = min(LH_TILE, blkEnd - base);
        __syncthreads();
        for (int i = tid; i < cnt; i += LH_THREADS)
            s_idx[i] = g_csr[base + i];
        __syncthreads();
        int lo = max(beg, base);
        int hi = min(end, base + cnt);
        #pragma unroll 4
        for (int j = lo; j < hi; ++j) {
            int s = s_idx[j - base];
            uint4 u = __ldg(h + (unsigned)s * 6 + c);
            float2 f0 = __half22float2(*reinterpret_cast<__half2*>(&u.x));
            float2 f1 = __half22float2(*reinterpret_cast<__half2*>(&u.y));
            float2 f2 = __half22float2(*reinterpret_cast<__half2*>(&u.z));
            float2 f3 = __half22float2(*reinterpret_cast<__half2*>(&u.w));
            a0 += f0.x; a1 += f0.y; a2 += f1.x; a3 += f1.y;
            a4 += f2.x; a5 += f2.y; a6 += f3.x; a7 += f3.y;
        }
    }

    if (node < N_NODES) {
        if (FINAL) {
            outf[(unsigned)node * 12 + c * 2]     = make_float4(a0, a1, a2, a3);
            outf[(unsigned)node * 12 + c * 2 + 1] = make_float4(a4, a5, a6, a7);
        } else {
            __half2 p0 = __floats2half2_rn(fmaxf(a0, 0.f), fmaxf(a1, 0.f));
            __half2 p1 = __floats2half2_rn(fmaxf(a2, 0.f), fmaxf(a3, 0.f));
            __half2 p2 = __floats2half2_rn(fmaxf(a4, 0.f), fmaxf(a5, 0.f));
            __half2 p3 = __floats2half2_rn(fmaxf(a6, 0.f), fmaxf(a7, 0.f));
            uint4 u;
            u.x = *reinterpret_cast<unsigned*>(&p0);
            u.y = *reinterpret_cast<unsigned*>(&p1);
            u.z = *reinterpret_cast<unsigned*>(&p2);
            u.w = *reinterpret_cast<unsigned*>(&p3);
            outh[(unsigned)node * 6 + c] = u;
        }
    }
}

extern "C" void kernel_launch(void* const* d_in, const int* in_sizes, int n_in,
                              void* d_out, int out_size) {
    const float4* features = (const float4*)d_in[0];
    const int*    src      = (const int*)d_in[1];
    const int*    dst      = (const int*)d_in[2];
    float4*       out      = (float4*)d_out;
    int n_edges = in_sizes[1];

    uint4 *h0 = nullptr, *buf0 = nullptr, *buf1 = nullptr;
    cudaGetSymbolAddress((void**)&h0,   g_h0);
    cudaGetSymbolAddress((void**)&buf0, g_buf0);
    cudaGetSymbolAddress((void**)&buf1, g_buf1);

    // ---- prep: zero counters + fp32->half feature convert (one kernel) ----
    prep_kernel<<<(N_NODES * 12 + 255) / 256, 256>>>(features);

    // ---- CSR build ----
    int n_quads = n_edges / 4;   // N_EDGES = 1.6M, divisible by 4
    hist_kernel<<<(n_quads + 255) / 256, 256>>>((const int4*)dst, n_quads);
    scanA_kernel<<<SCAN_BLOCKS, SCAN_BS>>>();
    scanC_kernel<<<SCAN_BLOCKS, SCAN_BS>>>();
    fill_kernel<<<(n_edges + 255) / 256, 256>>>(src, dst, n_edges);

    // ---- 3 layers, all half-gather ----
    int bh = (N_NODES + LH_NODES - 1) / LH_NODES;
    layer_h<false><<<bh, LH_THREADS>>>(h0,   buf0, nullptr);
    layer_h<false><<<bh, LH_THREADS>>>(buf0, buf1, nullptr);
    layer_h<true ><<<bh, LH_THREADS>>>(buf1, nullptr, out);
}

// round 8
// speedup vs baseline: 1.3773x; 1.3773x over previous
#include <cuda_runtime.h>
#include <cuda_fp16.h>
#include <cstdint>

#define N_NODES 100000
#define N_EDGES 1600000
#define D_FEAT 48

#define SCAN_BS 512
#define SCAN_BLOCKS ((N_NODES + SCAN_BS - 1) / SCAN_BS)   // 196

// ---- static device scratch (no allocation allowed) ----
__device__ int   g_row[N_NODES + 1];
__device__ int   g_cur[N_NODES];
__device__ int   g_csr[N_EDGES];
__device__ int   g_bsum[SCAN_BLOCKS];
__device__ uint4 g_buf0[N_NODES * 6];    // half[N,48] = 96B/row
__device__ uint4 g_buf1[N_NODES * 6];

// ---------------------------------------------------------------------------
// CSR build
// ---------------------------------------------------------------------------
__global__ void zero_deg_kernel() {
    int i = blockIdx.x * blockDim.x + threadIdx.x;
    if (i <= N_NODES) g_row[i] = 0;
}

__global__ void hist_kernel(const int4* __restrict__ dst4, int n_quads) {
    int q = blockIdx.x * blockDim.x + threadIdx.x;
    if (q < n_quads) {
        int4 d = dst4[q];
        atomicAdd(&g_row[d.x], 1);
        atomicAdd(&g_row[d.y], 1);
        atomicAdd(&g_row[d.z], 1);
        atomicAdd(&g_row[d.w], 1);
    }
}

__global__ void scanA_kernel() {
    __shared__ int s[SCAN_BS];
    int t = threadIdx.x;
    int i = blockIdx.x * SCAN_BS + t;
    s[t] = (i < N_NODES) ? g_row[i] : 0;
    __syncthreads();
    for (int off = SCAN_BS / 2; off > 0; off >>= 1) {
        if (t < off) s[t] += s[t + off];
        __syncthreads();
    }
    if (t == 0) g_bsum[blockIdx.x] = s[0];
}

// Local scan; each block derives its global offset by reducing the block
// aggregates below its id (196 ints) -- no serial middle kernel.
__global__ void scanC_kernel() {
    __shared__ int s[SCAN_BS];
    __shared__ int p[256];
    int t = threadIdx.x;
    int bid = blockIdx.x;

    if (t < 256) p[t] = (t < bid && t < SCAN_BLOCKS) ? g_bsum[t] : 0;
    __syncthreads();
    for (int off = 128; off > 0; off >>= 1) {
        if (t < off) p[t] += p[t + off];
        __syncthreads();
    }
    int blockPrefix = p[0];

    int i = bid * SCAN_BS + t;
    int v = (i < N_NODES) ? g_row[i] : 0;
    s[t] = v;
    __syncthreads();
    for (int off = 1; off < SCAN_BS; off <<= 1) {
        int x = (t >= off) ? s[t - off] : 0;
        __syncthreads();
        s[t] += x;
        __syncthreads();
    }
    if (i < N_NODES) {
        int excl = blockPrefix + s[t] - v;
        g_row[i] = excl;
        g_cur[i] = excl;
    }
    if (i == N_NODES - 1) g_row[N_NODES] = blockPrefix + s[t];
}

__global__ void fill_kernel(const int4* __restrict__ src4,
                            const int4* __restrict__ dst4, int n_quads) {
    int q = blockIdx.x * blockDim.x + threadIdx.x;
    if (q < n_quads) {
        int4 s = src4[q];
        int4 d = dst4[q];
        g_csr[atomicAdd(&g_cur[d.x], 1)] = s.x;
        g_csr[atomicAdd(&g_cur[d.y], 1)] = s.y;
        g_csr[atomicAdd(&g_cur[d.z], 1)] = s.z;
        g_csr[atomicAdd(&g_cur[d.w], 1)] = s.w;
    }
}

// ---------------------------------------------------------------------------
// Layer 1: fp32 features -> half buf (relu on store).
// 32 nodes/block x 12 chunk-threads.  (R5 geometry, known-good.)
// ---------------------------------------------------------------------------
#define L1_NODES 32
#define L1_THREADS (L1_NODES * 12)   // 384
#define L1_TILE 1024

__global__ void __launch_bounds__(L1_THREADS)
layer_f32_to_h(const float4* __restrict__ h, uint2* __restrict__ out) {
    __shared__ int s_idx[L1_TILE];
    int node0 = blockIdx.x * L1_NODES;
    int tid = threadIdx.x;
    int nl = tid / 12, c = tid - nl * 12;
    int node = node0 + nl;

    int lastn  = min(node0 + L1_NODES, N_NODES);
    int blkBeg = g_row[node0];
    int blkEnd = g_row[lastn];
    int beg = 0, end = 0;
    if (node < N_NODES) { beg = g_row[node]; end = g_row[node + 1]; }

    float4 acc = make_float4(0.f, 0.f, 0.f, 0.f);
    for (int base = blkBeg; base < blkEnd; base += L1_TILE) {
        int cnt = min(L1_TILE, blkEnd - base);
        __syncthreads();
        for (int i = tid; i < cnt; i += L1_THREADS)
            s_idx[i] = g_csr[base + i];
        __syncthreads();
        int lo = max(beg, base);
        int hi = min(end, base + cnt);
        #pragma unroll 4
        for (int j = lo; j < hi; ++j) {
            int s = s_idx[j - base];
            float4 v = __ldg(h + (unsigned)s * 12 + c);
            acc.x += v.x; acc.y += v.y; acc.z += v.z; acc.w += v.w;
        }
    }

    if (node < N_NODES) {
        __half2 a = __floats2half2_rn(fmaxf(acc.x, 0.f), fmaxf(acc.y, 0.f));
        __half2 b = __floats2half2_rn(fmaxf(acc.z, 0.f), fmaxf(acc.w, 0.f));
        uint2 u;
        u.x = *reinterpret_cast<unsigned*>(&a);
        u.y = *reinterpret_cast<unsigned*>(&b);
        out[(unsigned)node * 12 + c] = u;
    }
}

// ---------------------------------------------------------------------------
// Layers 2/3: half in. FINAL=false -> half out + relu; FINAL=true -> fp32 out.
// 32 nodes/block x 6 chunk-threads.  (R5 geometry, known-good.)
// ---------------------------------------------------------------------------
#define LH_NODES 32
#define LH_THREADS (LH_NODES * 6)    // 192
#define LH_TILE 1024

template <bool FINAL>
__global__ void __launch_bounds__(LH_THREADS)
layer_h(const uint4* __restrict__ h, uint4* __restrict__ outh,
        float4* __restrict__ outf) {
    __shared__ int s_idx[LH_TILE];
    int node0 = blockIdx.x * LH_NODES;
    int tid = threadIdx.x;
    int nl = tid / 6, c = tid - nl * 6;
    int node = node0 + nl;

    int lastn  = min(node0 + LH_NODES, N_NODES);
    int blkBeg = g_row[node0];
    int blkEnd = g_row[lastn];
    int beg = 0, end = 0;
    if (node < N_NODES) { beg = g_row[node]; end = g_row[node + 1]; }

    float a0 = 0.f, a1 = 0.f, a2 = 0.f, a3 = 0.f;
    float a4 = 0.f, a5 = 0.f, a6 = 0.f, a7 = 0.f;

    for (int base = blkBeg; base < blkEnd; base += LH_TILE) {
        int cnt = min(LH_TILE, blkEnd - base);
        __syncthreads();
        for (int i = tid; i < cnt; i += LH_THREADS)
            s_idx[i] = g_csr[base + i];
        __syncthreads();
        int lo = max(beg, base);
        int hi = min(end, base + cnt);
        #pragma unroll 4
        for (int j = lo; j < hi; ++j) {
            int s = s_idx[j - base];
            uint4 u = __ldg(h + (unsigned)s * 6 + c);
            float2 f0 = __half22float2(*reinterpret_cast<__half2*>(&u.x));
            float2 f1 = __half22float2(*reinterpret_cast<__half2*>(&u.y));
            float2 f2 = __half22float2(*reinterpret_cast<__half2*>(&u.z));
            float2 f3 = __half22float2(*reinterpret_cast<__half2*>(&u.w));
            a0 += f0.x; a1 += f0.y; a2 += f1.x; a3 += f1.y;
            a4 += f2.x; a5 += f2.y; a6 += f3.x; a7 += f3.y;
        }
    }

    if (node < N_NODES) {
        if (FINAL) {
            outf[(unsigned)node * 12 + c * 2]     = make_float4(a0, a1, a2, a3);
            outf[(unsigned)node * 12 + c * 2 + 1] = make_float4(a4, a5, a6, a7);
        } else {
            __half2 p0 = __floats2half2_rn(fmaxf(a0, 0.f), fmaxf(a1, 0.f));
            __half2 p1 = __floats2half2_rn(fmaxf(a2, 0.f), fmaxf(a3, 0.f));
            __half2 p2 = __floats2half2_rn(fmaxf(a4, 0.f), fmaxf(a5, 0.f));
            __half2 p3 = __floats2half2_rn(fmaxf(a6, 0.f), fmaxf(a7, 0.f));
            uint4 u;
            u.x = *reinterpret_cast<unsigned*>(&p0);
            u.y = *reinterpret_cast<unsigned*>(&p1);
            u.z = *reinterpret_cast<unsigned*>(&p2);
            u.w = *reinterpret_cast<unsigned*>(&p3);
            outh[(unsigned)node * 6 + c] = u;
        }
    }
}

extern "C" void kernel_launch(void* const* d_in, const int* in_sizes, int n_in,
                              void* d_out, int out_size) {
    const float4* features = (const float4*)d_in[0];
    const int*    src      = (const int*)d_in[1];
    const int*    dst      = (const int*)d_in[2];
    float4*       out      = (float4*)d_out;
    int n_edges = in_sizes[1];

    uint4 *buf0 = nullptr, *buf1 = nullptr;
    cudaGetSymbolAddress((void**)&buf0, g_buf0);
    cudaGetSymbolAddress((void**)&buf1, g_buf1);

    // ---- CSR build ----
    int n_quads = n_edges / 4;   // 1.6M edges, divisible by 4
    zero_deg_kernel<<<(N_NODES + 256) / 256, 256>>>();
    hist_kernel<<<(n_quads + 255) / 256, 256>>>((const int4*)dst, n_quads);
    scanA_kernel<<<SCAN_BLOCKS, SCAN_BS>>>();
    scanC_kernel<<<SCAN_BLOCKS, SCAN_BS>>>();
    fill_kernel<<<(n_quads + 255) / 256, 256>>>((const int4*)src,
                                                (const int4*)dst, n_quads);

    // ---- 3 layers (R5 geometry) ----
    int b1 = (N_NODES + L1_NODES - 1) / L1_NODES;
    int bh = (N_NODES + LH_NODES - 1) / LH_NODES;
    layer_f32_to_h<<<b1, L1_THREADS>>>(features, (uint2*)buf0);
    layer_h<false><<<bh, LH_THREADS>>>(buf0, buf1, nullptr);
    layer_h<true ><<<bh, LH_THREADS>>>(buf1, nullptr, out);
}